// round 16
// baseline (speedup 1.0000x reference)
#include <cuda_runtime.h>
#include <cuda_fp16.h>
#include <cstdint>

// ---------------- fp16 intermediates, ci-quad layout [ciq][px][4ci] ----------
#define SEG1 8388608LL
#define SEG2 10485760LL
__device__ __align__(16) ushort g_l0 [8 * 256 * 4096];
__device__ __align__(16) ushort g_l1 [8 * 256 * 1024];
__device__ __align__(16) ushort g_l2 [8 * 256 * 256];
__device__ __align__(16) ushort g_f  [8 * 256 * 5376];
__device__ __align__(16) ushort g_t1c[8 * 256 * 5376];
__device__ __align__(16) ushort g_t1r[8 * 256 * 5376];
__device__ __align__(16) ushort g_t2c[8 * 256 * 5376];
__device__ __align__(16) ushort g_t2r[8 * 256 * 5376];
__device__ __align__(16) float g_sk1[2 * 8 * 256 * 1024];
__device__ __align__(16) float g_sk2[4 * 8 * 256 * 256];

// ---------------- fp16 weight arena (t-major K layout) -----------------------
#define WOFF_L0  0LL
#define WOFF_L1  131072LL
#define WOFF_L2  393216LL
#define WOFF_FW0 917504LL
#define WOFF_FW1 1507328LL
#define WOFF_FW2 2097152LL
#define WOFF_CW0 2686976LL
#define WOFF_CW1 3276800LL
#define WOFF_CW2 3866624LL
#define WOFF_RW0 4456448LL
#define WOFF_RW1 5046272LL
#define WOFF_RW2 5636096LL
#define WARENA   5672960LL
__device__ __align__(16) ushort g_wh[WARENA];

// ---------------- helpers ----------------------------------------------------
#define SWZ(off)  ((off) ^ (((off) >> 3) & 0x70))   // 128B-row swizzle
#define SWZA(off) ((off) ^ (((off) >> 4) & 0x70))   // 256B-row swizzle

static __device__ __forceinline__ uint32_t smem_u32(const void* p) {
    uint32_t a;
    asm("{ .reg .u64 t; cvta.to.shared.u64 t, %1; cvt.u32.u64 %0, t; }"
        : "=r"(a) : "l"(p));
    return a;
}

#define LDSM_X4(r0, r1, r2, r3, ad) \
    asm volatile("ldmatrix.sync.aligned.m8n8.x4.shared.b16 {%0,%1,%2,%3}, [%4];" \
                 : "=r"(r0), "=r"(r1), "=r"(r2), "=r"(r3) : "r"(ad))
#define LDSM_X4T(r0, r1, r2, r3, ad) \
    asm volatile("ldmatrix.sync.aligned.m8n8.x4.trans.shared.b16 {%0,%1,%2,%3}, [%4];" \
                 : "=r"(r0), "=r"(r1), "=r"(r2), "=r"(r3) : "r"(ad))
#define LDSM_X2(r0, r1, ad) \
    asm volatile("ldmatrix.sync.aligned.m8n8.x2.shared.b16 {%0,%1}, [%2];" \
                 : "=r"(r0), "=r"(r1) : "r"(ad))
#define MMA16816(d, a, b) \
    asm volatile("mma.sync.aligned.m16n8k16.row.col.f32.f16.f16.f32 " \
                 "{%0,%1,%2,%3},{%4,%5,%6,%7},{%8,%9},{%0,%1,%2,%3};" \
                 : "+f"((d)[0]), "+f"((d)[1]), "+f"((d)[2]), "+f"((d)[3]) \
                 : "r"((a)[0]), "r"((a)[1]), "r"((a)[2]), "r"((a)[3]), \
                   "r"((b)[0]), "r"((b)[1]))
#define CVT2HF(dst, hi, lo) \
    asm("cvt.rn.f16x2.f32 %0, %1, %2;" : "=r"(dst) : "f"(hi), "f"(lo))
#define CP_ASYNC16(dst, src) \
    asm volatile("cp.async.cg.shared.global [%0], [%1], 16;" :: "r"(dst), "l"(src))
#define CP_ASYNC8Z(dst, src, sz) \
    asm volatile("cp.async.ca.shared.global [%0], [%1], 8, %2;" \
                 :: "r"(dst), "l"(src), "r"(sz))
#define CP_COMMIT() asm volatile("cp.async.commit_group;" ::: "memory")
#define CP_WAIT0()  asm volatile("cp.async.wait_group 0;" ::: "memory")

static __device__ __forceinline__ ushort f2h(float v) {
    return __half_as_ushort(__float2half_rn(v));
}
static __device__ __forceinline__ float h2f(ushort u) {
    return __half2float(__ushort_as_half(u));
}

// ---------------- merged weight pre-transform --------------------------------
struct WtEnt { const float* src; long long start; int coutA; int cin; int taps; };
struct WtTab { WtEnt e[12]; };

__global__ void wt_all(WtTab T, ushort* __restrict__ wh)
{
    long long idx = (long long)blockIdx.x * 256 + threadIdx.x;
    if (idx >= WARENA) return;
    int i = 0;
#pragma unroll
    for (int j = 1; j < 12; ++j) if (idx >= T.e[j].start) i = j;
    const WtEnt E = T.e[i];
    long long local = idx - E.start;
    const int Kk = E.cin * E.taps;
    long long co = local / Kk;
    int r  = (int)(local - co * Kk);
    int t  = r / E.cin;
    int ci = r - t * E.cin;
    float v = 0.f;
    if (co < E.coutA) v = E.src[co * Kk + (long long)ci * E.taps + t];
    wh[idx] = f2h(v);
}

// ---------------- merged balanced lateral 1x1 GEMMs --------------------------
struct LatEnt {
    const float* in; const ushort* w; const float* bias; void* out;
    int Cin; int logW; long long sliceStride; int split;
};
struct LatTab { LatEnt e[3]; };

__global__ void __launch_bounds__(256, 2)
lat_all(LatTab L)
{
    extern __shared__ char dsm[];
    const int tid = threadIdx.x;
    uint32_t u0  = smem_u32(dsm);
    uint32_t pad = (1024u - (u0 & 1023u)) & 1023u;
    char*    db  = dsm + pad;
    uint32_t dyn = u0 + pad;

    const int bx = blockIdx.x;
    int which, xq, yb;
    if (bx < 64)      { which = 0; xq = bx & 31; yb = bx >> 5; }
    else if (bx < 96) { int l = bx - 64; which = 1; xq = l & 7; yb = l >> 3; }
    else              { int l = bx - 96; which = 2; xq = l & 1; yb = l >> 1; }
    const LatEnt E = L.e[which];

    const int coTile = yb & 1, slice = yb >> 1;
    const int HW = 1 << (2 * E.logW);
    const int co0 = coTile * 128;
    const int bz  = blockIdx.z;
    const int p0  = xq * 128;
    const int c0  = E.split ? slice * 8 : 0;
    const int K   = E.Cin;
    const float* __restrict__ in = E.in;
    const ushort* wh = E.w;

    const int wid = tid >> 5, lane = tid & 31;
    const int m_base = (wid & 3) * 32;
    const int n_base = (wid >> 2) * 64;
    const int g = lane >> 3, lr = lane & 7;

    const uint32_t aA = dyn;
    const uint32_t bA = dyn + 16384;

    float acc[2][8][4];
#pragma unroll
    for (int mt = 0; mt < 2; ++mt)
#pragma unroll
        for (int nt = 0; nt < 8; ++nt)
#pragma unroll
            for (int r = 0; r < 4; ++r) acc[mt][nt][r] = 0.f;

#pragma unroll 1
    for (int cc = 0; cc < 8; ++cc) {
        const int k0 = (c0 + cc) << 6;
#pragma unroll
        for (int j = 0; j < 8; ++j) {
            int idx = tid + j * 256;
            int k = idx >> 5, q = idx & 31;
            const float4 f4 = *(const float4*)(in +
                ((long long)(bz * K + k0 + k)) * HW + p0 + q * 4);
            uint32_t h01, h23;
            CVT2HF(h01, f4.y, f4.x);
            CVT2HF(h23, f4.w, f4.z);
            uint32_t off = SWZA((uint32_t)k * 256u + (uint32_t)q * 8u);
            *(uint2*)(db + off) = make_uint2(h01, h23);
        }
        {
            const char* sH = (const char*)(wh + (long long)co0 * K + k0);
            const long long rowb = (long long)K * 2;
#pragma unroll
            for (int j = 0; j < 4; ++j) {
                int idx = tid + j * 256;
                int r = idx >> 3, c = idx & 7;
                uint4 hv = *(const uint4*)(sH + r * rowb + c * 16);
                uint32_t off = SWZ((uint32_t)r * 128u + (uint32_t)c * 16u);
                *(uint4*)(db + 16384 + off) = hv;
            }
        }
        __syncthreads();

#pragma unroll
        for (int s = 0; s < 4; ++s) {
            uint32_t bh[8][2];
#pragma unroll
            for (int np = 0; np < 4; ++np) {
                int nrow = n_base + np * 16 + (g >> 1) * 8 + lr;
                uint32_t ad = bA + SWZ((uint32_t)(nrow * 128 + s * 32 + (g & 1) * 16));
                LDSM_X4(bh[np*2][0], bh[np*2][1], bh[np*2+1][0], bh[np*2+1][1], ad);
            }
            uint32_t ah[2][4];
#pragma unroll
            for (int mt = 0; mt < 2; ++mt) {
                int krow = s * 16 + (g >> 1) * 8 + lr;
                int colb = (m_base + mt * 16 + (g & 1) * 8) * 2;
                uint32_t ad = aA + SWZA((uint32_t)(krow * 256 + colb));
                LDSM_X4T(ah[mt][0], ah[mt][1], ah[mt][2], ah[mt][3], ad);
            }
#pragma unroll
            for (int mt = 0; mt < 2; ++mt)
#pragma unroll
                for (int nt = 0; nt < 8; ++nt)
                    MMA16816(acc[mt][nt], ah[mt], bh[nt]);
        }
        __syncthreads();
    }

#pragma unroll
    for (int mt = 0; mt < 2; ++mt)
#pragma unroll
        for (int nt = 0; nt < 8; ++nt) {
            if (E.split) {
#pragma unroll
                for (int rg = 0; rg < 4; ++rg) {
                    int m  = m_base + mt * 16 + (lane >> 2) + ((rg >= 2) ? 8 : 0);
                    int co = co0 + n_base + nt * 8 + (lane & 3) * 2 + (rg & 1);
                    long long off = ((long long)(bz * 256 + co)) * HW + p0 + m;
                    ((float*)E.out)[slice * E.sliceStride + off] = acc[mt][nt][rg];
                }
            } else {
#pragma unroll
                for (int r2 = 0; r2 < 2; ++r2) {
                    int m  = m_base + mt * 16 + (lane >> 2) + r2 * 8;
                    int co = co0 + n_base + nt * 8 + (lane & 3) * 2;
                    float v0 = acc[mt][nt][r2 * 2 + 0] + E.bias[co];
                    float v1 = acc[mt][nt][r2 * 2 + 1] + E.bias[co + 1];
                    uint32_t pk = (uint32_t)f2h(v0) | ((uint32_t)f2h(v1) << 16);
                    long long a32 = (((long long)(bz * 64 + (co >> 2))) * HW + p0 + m) * 2
                                    + ((co >> 1) & 1);
                    ((unsigned*)E.out)[a32] = pk;
                }
            }
        }
}

// ---------------- merged split-K reduces (+bias, fp16 quad out) --------------
__global__ void red_all(const float* __restrict__ sk1, const float* __restrict__ sk2,
                        ushort* __restrict__ l1, ushort* __restrict__ l2,
                        const float* __restrict__ b1, const float* __restrict__ b2)
{
    const long long n1 = 8LL * 256 * 1024;
    const long long n2 = 8LL * 256 * 256;
    long long idx = (long long)blockIdx.x * 256 + threadIdx.x;
    if (idx < n1) {
        const int HW = 1024;
        int px = (int)(idx & (HW - 1));
        int co = (int)((idx >> 10) & 255);
        int bz = (int)(idx >> 18);
        float v = b1[co] + sk1[idx] + sk1[n1 + idx];
        l1[(((long long)(bz * 64 + (co >> 2))) * HW + px) * 4 + (co & 3)] = f2h(v);
    } else if (idx < n1 + n2) {
        long long id2 = idx - n1;
        const int HW = 256;
        int px = (int)(id2 & (HW - 1));
        int co = (int)((id2 >> 8) & 255);
        int bz = (int)(id2 >> 16);
        float v = b2[co];
#pragma unroll
        for (int s = 0; s < 4; ++s) v += sk2[s * n2 + id2];
        l2[(((long long)(bz * 64 + (co >> 2))) * HW + px) * 4 + (co & 3)] = f2h(v);
    }
}

// ---------------- nearest 2x upsample + add (fp16 quad domain) ---------------
__global__ void up2add_kernel(unsigned* __restrict__ big,
                              const unsigned* __restrict__ small, int logWs)
{
    const int Ws = 1 << logWs;
    const int W  = Ws * 2;
    const long long total = 8LL * 64 * W * W * 2;
    long long idx = (long long)blockIdx.x * blockDim.x + threadIdx.x;
    if (idx >= total) return;
    int inner2 = (int)(idx & 1);
    long long rest = idx >> 1;
    int x = (int)(rest & (W - 1));
    int y = (int)((rest >> (logWs + 1)) & (W - 1));
    long long bcq = rest >> (2 * logWs + 2);
    unsigned sb = small[(((bcq << logWs) + (y >> 1)) * Ws + (x >> 1)) * 2 + inner2];
    unsigned bb = big[idx];
    float v0 = h2f((ushort)(bb & 0xFFFF)) + h2f((ushort)(sb & 0xFFFF));
    float v1 = h2f((ushort)(bb >> 16))   + h2f((ushort)(sb >> 16));
    big[idx] = (uint32_t)f2h(v0) | ((uint32_t)f2h(v1) << 16);
}

// ---------------- 3x3 tower GEMM: double-buffered A halo + B ------------------
struct TArgs {
    const ushort* in[6];
    void* out[6];
    const ushort* wh[6];
    const float* bias[6];
    long long ob[6];
    int coutA[6];
};

#define A_BASE 0u
#define A_BUFSZ 34816u
#define B_BASE 69632u
#define B_BUFSZ 16384u
#define TOWER_DYN 102400
static const size_t TOWER_SMEM = TOWER_DYN + 1024;

template <int NTILE>
static __device__ __forceinline__ void stage_B_async(
    uint32_t bdst, const ushort* wh, int co0, int k0, int tid)
{
    const char* sH = (const char*)(wh + (long long)co0 * 2304 + k0);
    const long long rowb = 4608;
#pragma unroll
    for (int j = 0; j < (NTILE * 8 + 255) / 256; ++j) {
        int idx = tid + j * 256;
        if (idx < NTILE * 8) {
            int r = idx >> 3, c = idx & 7;
            uint32_t off = SWZ((uint32_t)r * 128u + (uint32_t)c * 16u);
            CP_ASYNC16(bdst + off, sH + r * rowb + c * 16);
        }
    }
}

template <int LVL>
static __device__ __forceinline__ void stage_A_async(
    uint32_t adst, const uint2* __restrict__ inq, int bz, int cic, int y0, int tid)
{
    constexpr int logW = 6 - LVL;
    constexpr int W    = 1 << logW;
    constexpr int padW = W + 2;
    constexpr int imgR = (128 >> logW) + 2;
    constexpr int Rows = imgR * padW;
    constexpr int RowsPad = (Rows + 15) & ~15;
    constexpr int itersA = (RowsPad * 16) / 256;
    constexpr int HW = 1 << (2 * logW);
#pragma unroll
    for (int i = 0; i < itersA; ++i) {
        int e = tid + i * 256;
        int j = e / RowsPad;
        int r = e - j * RowsPad;
        int iy = r / padW;
        int ix = r - iy * padW;
        int yi = y0 - 1 + iy;
        int xv = ix - 1;
        bool ok = (r < Rows) && ((unsigned)yi < (unsigned)W) &&
                  ((unsigned)xv < (unsigned)W);
        const uint2* src = ok
            ? inq + ((long long)(bz * 64 + cic * 16 + j)) * HW + yi * W + xv
            : inq;
        uint32_t off = SWZ((uint32_t)r * 128u + (uint32_t)j * 8u);
        CP_ASYNC8Z(adst + off, src, ok ? 8 : 0);
    }
}

// OUTP=true  : write packed fp16 quad-layout intermediate
// OUTP=false : stage fp32 tile in smem, then fully-coalesced float4 copy to d_out
template <int LVL, int NTILE, bool RELU, bool OUTP>
static __device__ __forceinline__ void tower_body(
    const TArgs& T, char* db, uint32_t dyn,
    int xl, int idx6, int coTile, int tid, int bz)
{
    constexpr int logW = 6 - LVL;
    constexpr int W    = 1 << logW;
    constexpr int padW = W + 2;
    constexpr int HW = 1 << (2 * logW);

    const uint2* __restrict__ inq = (const uint2*)T.in[idx6];
    const ushort* wh = T.wh[idx6];
    const float* bias = T.bias[idx6];

    const int p0  = xl * 128;
    const int y0  = p0 >> logW;
    const int co0 = coTile * NTILE;

    constexpr int WN  = NTILE / 2;
    constexpr int N8T = WN / 8;
    const int wid = tid >> 5, lane = tid & 31;
    const int m_base = (wid & 3) * 32;
    const int n_base = (wid >> 2) * WN;
    const int g = lane >> 3, lr = lane & 7;

    float acc[2][N8T][4];
#pragma unroll
    for (int mt = 0; mt < 2; ++mt)
#pragma unroll
        for (int nt = 0; nt < N8T; ++nt)
#pragma unroll
            for (int r = 0; r < 4; ++r) acc[mt][nt][r] = 0.f;

    // ---- prologue: A(cic0) + B(tt0) ----
    stage_A_async<LVL>(dyn + A_BASE, inq, bz, 0, y0, tid);
    stage_B_async<NTILE>(dyn + B_BASE, wh, co0, 0, tid);
    CP_COMMIT();
    CP_WAIT0();
    __syncthreads();

    // ---- continuous 36-tap pipeline: tt = cic*9 + t ----
    for (int cic = 0; cic < 4; ++cic) {
        const uint32_t aBase = dyn + A_BASE + (uint32_t)((cic & 1) * A_BUFSZ);
        for (int t = 0; t < 9; ++t) {
            const int tt = cic * 9 + t;
            if (tt < 35) {
                const int nt_  = tt + 1;
                const int ncic = nt_ / 9, ntap = nt_ - ncic * 9;
                stage_B_async<NTILE>(dyn + B_BASE + (uint32_t)((nt_ & 1) * B_BUFSZ),
                                     wh, co0, ntap * 256 + ncic * 64, tid);
                if (t == 8)
                    stage_A_async<LVL>(dyn + A_BASE + (uint32_t)(((cic + 1) & 1) * A_BUFSZ),
                                       inq, bz, cic + 1, y0, tid);
                CP_COMMIT();
            }
            const uint32_t bA = dyn + B_BASE + (uint32_t)((tt & 1) * B_BUFSZ);

            const int dy = t / 3 - 1;
            const int dx = t - (t / 3) * 3 - 1;
            int prow[2];
#pragma unroll
            for (int mt = 0; mt < 2; ++mt) {
                int m = m_base + mt * 16 + ((g & 1) << 3) + lr;
                prow[mt] = (1 + (m >> logW) + dy) * padW + (m & (W - 1)) + 1 + dx;
            }
            const int colA0 = (g >> 1) * 16;

#pragma unroll
            for (int s = 0; s < 4; ++s) {
                uint32_t bh[N8T][2];
                if constexpr (N8T == 1) {
                    uint32_t ad = bA +
                        SWZ((uint32_t)((n_base + lr) * 128 + s * 32 + (g & 1) * 16));
                    LDSM_X2(bh[0][0], bh[0][1], ad);
                } else {
#pragma unroll
                    for (int np = 0; np < N8T / 2; ++np) {
                        int nrow = n_base + np * 16 + (g >> 1) * 8 + lr;
                        uint32_t ad = bA +
                            SWZ((uint32_t)(nrow * 128 + s * 32 + (g & 1) * 16));
                        LDSM_X4(bh[np*2][0], bh[np*2][1], bh[np*2+1][0], bh[np*2+1][1], ad);
                    }
                }
                uint32_t ah[2][4];
#pragma unroll
                for (int mt = 0; mt < 2; ++mt) {
                    uint32_t ad = aBase +
                        SWZ((uint32_t)(prow[mt] * 128 + s * 32 + colA0));
                    LDSM_X4(ah[mt][0], ah[mt][1], ah[mt][2], ah[mt][3], ad);
                }
#pragma unroll
                for (int mt = 0; mt < 2; ++mt)
#pragma unroll
                    for (int nt = 0; nt < N8T; ++nt)
                        MMA16816(acc[mt][nt], ah[mt], bh[nt]);
            }
            if (tt < 35) CP_WAIT0();
            __syncthreads();
        }
    }

    // ---- epilogue ----
    if constexpr (OUTP) {
#pragma unroll
        for (int mt = 0; mt < 2; ++mt)
#pragma unroll
            for (int nt = 0; nt < N8T; ++nt)
#pragma unroll
                for (int r2 = 0; r2 < 2; ++r2) {
                    int m  = m_base + mt * 16 + (lane >> 2) + r2 * 8;
                    int co = co0 + n_base + nt * 8 + (lane & 3) * 2;
                    float v0 = acc[mt][nt][r2 * 2 + 0] + bias[co];
                    float v1 = acc[mt][nt][r2 * 2 + 1] + bias[co + 1];
                    if (RELU) { v0 = fmaxf(v0, 0.f); v1 = fmaxf(v1, 0.f); }
                    uint32_t pk = (uint32_t)f2h(v0) | ((uint32_t)f2h(v1) << 16);
                    long long a32 = (((long long)(bz * 64 + (co >> 2))) * HW + p0 + m) * 2
                                    + ((co >> 1) & 1);
                    ((unsigned*)T.out[idx6])[a32] = pk;
                }
    } else {
        float* st = (float*)db;
#pragma unroll
        for (int mt = 0; mt < 2; ++mt)
#pragma unroll
            for (int nt = 0; nt < N8T; ++nt)
#pragma unroll
                for (int r2 = 0; r2 < 2; ++r2) {
                    int m    = m_base + mt * 16 + (lane >> 2) + r2 * 8;
                    int cloc = n_base + nt * 8 + (lane & 3) * 2;
                    float v0 = acc[mt][nt][r2 * 2 + 0] + bias[co0 + cloc];
                    float v1 = acc[mt][nt][r2 * 2 + 1] + bias[co0 + cloc + 1];
                    *(float2*)&st[m * 132 + cloc] = make_float2(v0, v1);
                }
        __syncthreads();
        int cols = T.coutA[idx6] - co0;
        if (cols > NTILE) cols = NTILE;
        const int q4 = cols >> 2;
        float* dst = (float*)T.out[idx6] + (long long)bz * T.ob[idx6] + co0;
        for (int e = tid; e < 128 * q4; e += 256) {
            int m  = e / q4;
            int c4 = e - m * q4;
            float4 v = *(float4*)&st[m * 132 + c4 * 4];
            *(float4*)(dst + (long long)(p0 + m) * 252 + c4 * 4) = v;
        }
    }
}

template <int NTILE, bool RELU, bool OUTP>
__global__ void __launch_bounds__(256, 2)
tower_gemm(TArgs T)
{
    extern __shared__ char dsm[];
    const int tid = threadIdx.x;
    uint32_t u0  = smem_u32(dsm);
    uint32_t padB = (1024u - (u0 & 1023u)) & 1023u;
    char*    db  = dsm + padB;
    uint32_t dyn = u0 + padB;

    const int xb  = blockIdx.x;
    const int lvl = (xb >= 40) ? 2 : ((xb >= 32) ? 1 : 0);
    const int xl  = xb - ((lvl == 2) ? 40 : ((lvl == 1) ? 32 : 0));
    const int yb  = blockIdx.y;
    const int set = yb >> 1;
    const int coTile = yb & 1;
    const int idx6 = set * 3 + lvl;
    const int bz  = blockIdx.z;

    if (lvl == 0)
        tower_body<0, NTILE, RELU, OUTP>(T, db, dyn, xl, idx6, coTile, tid, bz);
    else if (lvl == 1)
        tower_body<1, NTILE, RELU, OUTP>(T, db, dyn, xl, idx6, coTile, tid, bz);
    else
        tower_body<2, NTILE, RELU, OUTP>(T, db, dyn, xl, idx6, coTile, tid, bz);
}

// merged finals: y in {0,1} -> cls (NTILE=128, set 0); y == 2 -> reg (NTILE=16, set 1)
__global__ void __launch_bounds__(256, 2)
tower_finals(TArgs T)
{
    extern __shared__ char dsm[];
    const int tid = threadIdx.x;
    uint32_t u0  = smem_u32(dsm);
    uint32_t padB = (1024u - (u0 & 1023u)) & 1023u;
    char*    db  = dsm + padB;
    uint32_t dyn = u0 + padB;

    const int xb  = blockIdx.x;
    const int lvl = (xb >= 40) ? 2 : ((xb >= 32) ? 1 : 0);
    const int xl  = xb - ((lvl == 2) ? 40 : ((lvl == 1) ? 32 : 0));
    const int yb  = blockIdx.y;
    const int bz  = blockIdx.z;

    if (yb < 2) {
        const int idx6 = lvl;
        if (lvl == 0)      tower_body<0, 128, false, false>(T, db, dyn, xl, idx6, yb, tid, bz);
        else if (lvl == 1) tower_body<1, 128, false, false>(T, db, dyn, xl, idx6, yb, tid, bz);
        else               tower_body<2, 128, false, false>(T, db, dyn, xl, idx6, yb, tid, bz);
    } else {
        const int idx6 = 3 + lvl;
        if (lvl == 0)      tower_body<0, 16, false, false>(T, db, dyn, xl, idx6, 0, tid, bz);
        else if (lvl == 1) tower_body<1, 16, false, false>(T, db, dyn, xl, idx6, 0, tid, bz);
        else               tower_body<2, 16, false, false>(T, db, dyn, xl, idx6, 0, tid, bz);
    }
}

// ---------------- anchors ----------------------------------------------------
__global__ void anchors_kernel(float* __restrict__ out)
{
    int i = blockIdx.x * blockDim.x + threadIdx.x;
    if (i >= 16128) return;
    int lvl, rem;
    if (i < 12288)      { lvl = 0; rem = i; }
    else if (i < 15360) { lvl = 1; rem = i - 12288; }
    else                { lvl = 2; rem = i - 15360; }
    const int w        = 64 >> lvl;
    const float stride = 8.0f * (float)(1 << lvl);
    const float bs     = 32.0f * (float)(1 << lvl);
    const int a = rem % 3;
    const int s = rem / 3;
    const int x = s % w;
    const int y = s / w;
    const float sq[3] = {0.70710678118654752f, 1.0f, 1.41421356237309505f};
    const float hw = bs * sq[a] * 0.5f;
    const float hh = bs / sq[a] * 0.5f;
    const float cx = (float)x * stride;
    const float cy = (float)y * stride;
    float* o = out + (long long)i * 4;
    o[0] = cx - hw; o[1] = cy - hh; o[2] = cx + hw; o[3] = cy + hh;
}

// ---------------- host dispatch ----------------------------------------------
static const size_t LAT_SMEM = 33792;

extern "C" void kernel_launch(void* const* d_in, const int* in_sizes, int n_in,
                              void* d_out, int out_size)
{
    const float* feat3 = (const float*)d_in[0];
    const float* feat4 = (const float*)d_in[1];
    const float* feat5 = (const float*)d_in[2];
    const float* lw0 = (const float*)d_in[3];  const float* lb0 = (const float*)d_in[4];
    const float* lw1 = (const float*)d_in[5];  const float* lb1 = (const float*)d_in[6];
    const float* lw2 = (const float*)d_in[7];  const float* lb2 = (const float*)d_in[8];
    const float* fw0 = (const float*)d_in[9];  const float* fb0 = (const float*)d_in[10];
    const float* fw1 = (const float*)d_in[11]; const float* fb1 = (const float*)d_in[12];
    const float* fw2 = (const float*)d_in[13]; const float* fb2 = (const float*)d_in[14];
    const float* cw0 = (const float*)d_in[15]; const float* cb0 = (const float*)d_in[16];
    const float* cw1 = (const float*)d_in[17]; const float* cb1 = (const float*)d_in[18];
    const float* cw2 = (const float*)d_in[19]; const float* cb2 = (const float*)d_in[20];
    const float* rw0 = (const float*)d_in[21]; const float* rb0 = (const float*)d_in[22];
    const float* rw1 = (const float*)d_in[23]; const float* rb1 = (const float*)d_in[24];
    const float* rw2 = (const float*)d_in[25]; const float* rb2 = (const float*)d_in[26];
    float* out = (float*)d_out;

    cudaFuncSetAttribute(lat_all, cudaFuncAttributeMaxDynamicSharedMemorySize, (int)LAT_SMEM);
    cudaFuncSetAttribute(tower_gemm<128, false, true>, cudaFuncAttributeMaxDynamicSharedMemorySize, (int)TOWER_SMEM);
    cudaFuncSetAttribute(tower_gemm<128, true,  true>, cudaFuncAttributeMaxDynamicSharedMemorySize, (int)TOWER_SMEM);
    cudaFuncSetAttribute(tower_finals, cudaFuncAttributeMaxDynamicSharedMemorySize, (int)TOWER_SMEM);

    ushort *l0, *l1, *l2, *f, *t1c, *t1r, *t2c, *t2r, *wh;
    float *sk1, *sk2;
    cudaGetSymbolAddress((void**)&l0,  g_l0);
    cudaGetSymbolAddress((void**)&l1,  g_l1);
    cudaGetSymbolAddress((void**)&l2,  g_l2);
    cudaGetSymbolAddress((void**)&f,   g_f);
    cudaGetSymbolAddress((void**)&t1c, g_t1c);
    cudaGetSymbolAddress((void**)&t1r, g_t1r);
    cudaGetSymbolAddress((void**)&t2c, g_t2c);
    cudaGetSymbolAddress((void**)&t2r, g_t2r);
    cudaGetSymbolAddress((void**)&sk1, g_sk1);
    cudaGetSymbolAddress((void**)&sk2, g_sk2);
    cudaGetSymbolAddress((void**)&wh,  g_wh);

    {
        WtTab T;
        const WtEnt ents[12] = {
            { lw0, WOFF_L0,  256, 512,  1 },
            { lw1, WOFF_L1,  256, 1024, 1 },
            { lw2, WOFF_L2,  256, 2048, 1 },
            { fw0, WOFF_FW0, 256, 256,  9 },
            { fw1, WOFF_FW1, 256, 256,  9 },
            { fw2, WOFF_FW2, 256, 256,  9 },
            { cw0, WOFF_CW0, 256, 256,  9 },
            { cw1, WOFF_CW1, 256, 256,  9 },
            { cw2, WOFF_CW2, 240, 256,  9 },
            { rw0, WOFF_RW0, 256, 256,  9 },
            { rw1, WOFF_RW1, 256, 256,  9 },
            { rw2, WOFF_RW2, 12,  256,  9 },
        };
        for (int i = 0; i < 12; ++i) T.e[i] = ents[i];
        wt_all<<<(unsigned)((WARENA + 255) / 256), 256>>>(T, wh);
    }

    // ---- merged balanced FPN laterals ----
    {
        LatTab L;
        L.e[0] = { feat3, wh + WOFF_L0, lb0, l0,  512,  6, 0, 0 };
        L.e[1] = { feat4, wh + WOFF_L1, lb1, sk1, 1024, 5, 8LL * 256 * 1024, 1 };
        L.e[2] = { feat5, wh + WOFF_L2, lb2, sk2, 2048, 4, 8LL * 256 * 256,  1 };
        lat_all<<<dim3(112, 1, 8), 256, LAT_SMEM>>>(L);
    }
    {
        long long n = 8LL * 256 * 1024 + 8LL * 256 * 256;
        red_all<<<(unsigned)((n + 255) / 256), 256>>>(sk1, sk2, l1, l2, lb1, lb2);
    }
    {
        long long n1 = 8LL * 64 * 32 * 32 * 2;
        up2add_kernel<<<(unsigned)((n1 + 255) / 256), 256>>>(
            (unsigned*)l1, (const unsigned*)l2, 4);
        long long n0 = 8LL * 64 * 64 * 64 * 2;
        up2add_kernel<<<(unsigned)((n0 + 255) / 256), 256>>>(
            (unsigned*)l0, (const unsigned*)l1, 5);
    }

    auto setSlot = [&](TArgs& T, int s, const ushort* i0, const ushort* i1,
                       const ushort* i2, void* o0, void* o1, void* o2,
                       long long woff, const float* b, int coutA) {
        T.in[s*3+0] = i0; T.in[s*3+1] = i1; T.in[s*3+2] = i2;
        T.out[s*3+0] = o0; T.out[s*3+1] = o1; T.out[s*3+2] = o2;
        for (int l = 0; l < 3; ++l) {
            T.wh[s*3+l] = wh + woff;
            T.bias[s*3+l] = b;
            T.ob[s*3+l] = 5376LL * 252;
            T.coutA[s*3+l] = coutA;
        }
    };

    // FPN 3x3 output convs (per-level weights)
    {
        TArgs T;
        T.in[0] = l0; T.in[1] = l1; T.in[2] = l2;
        T.out[0] = f; T.out[1] = f + SEG1; T.out[2] = f + SEG2;
        const long long wo[3] = { WOFF_FW0, WOFF_FW1, WOFF_FW2 };
        const float* bb[3] = { fb0, fb1, fb2 };
        for (int l = 0; l < 3; ++l) {
            T.wh[l] = wh + wo[l]; T.bias[l] = bb[l];
            T.ob[l] = 0; T.coutA[l] = 256;
        }
        tower_gemm<128, false, true><<<dim3(42, 2, 8), 256, TOWER_SMEM>>>(T);
    }
    // conv1 fused (cls set 0, reg set 1)
    {
        TArgs T;
        setSlot(T, 0, f, f + SEG1, f + SEG2, t1c, t1c + SEG1, t1c + SEG2, WOFF_CW0, cb0, 256);
        setSlot(T, 1, f, f + SEG1, f + SEG2, t1r, t1r + SEG1, t1r + SEG2, WOFF_RW0, rb0, 256);
        tower_gemm<128, true, true><<<dim3(42, 4, 8), 256, TOWER_SMEM>>>(T);
    }
    // conv2 fused
    {
        TArgs T;
        setSlot(T, 0, t1c, t1c + SEG1, t1c + SEG2, t2c, t2c + SEG1, t2c + SEG2, WOFF_CW1, cb1, 256);
        setSlot(T, 1, t1r, t1r + SEG1, t1r + SEG2, t2r, t2r + SEG1, t2r + SEG2, WOFF_RW1, rb1, 256);
        tower_gemm<128, true, true><<<dim3(42, 4, 8), 256, TOWER_SMEM>>>(T);
    }
    // merged finals: cls (y=0,1) + reg (y=2)
    {
        TArgs T;
        setSlot(T, 0, t2c, t2c + SEG1, t2c + SEG2,
                out, out + 4096LL * 252, out + 5120LL * 252, WOFF_CW2, cb2, 240);
        setSlot(T, 1, t2r, t2r + SEG1, t2r + SEG2,
                out + 240, out + 4096LL * 252 + 240, out + 5120LL * 252 + 240,
                WOFF_RW2, rb2, 12);
        tower_finals<<<dim3(42, 3, 8), 256, TOWER_SMEM>>>(T);
    }

    anchors_kernel<<<(16128 + 255) / 256, 256>>>(out + 10838016LL);
}

// round 17
// speedup vs baseline: 1.1438x; 1.1438x over previous
#include <cuda_runtime.h>
#include <cuda_fp16.h>
#include <cstdint>

// ---------------- fp16 intermediates, ci-quad layout [ciq][px][4ci] ----------
#define SEG1 8388608LL
#define SEG2 10485760LL
__device__ __align__(16) ushort g_l0 [8 * 256 * 4096];
__device__ __align__(16) ushort g_l1 [8 * 256 * 1024];
__device__ __align__(16) ushort g_l2 [8 * 256 * 256];
__device__ __align__(16) ushort g_f  [8 * 256 * 5376];
__device__ __align__(16) ushort g_t1c[8 * 256 * 5376];
__device__ __align__(16) ushort g_t1r[8 * 256 * 5376];
__device__ __align__(16) ushort g_t2c[8 * 256 * 5376];
__device__ __align__(16) ushort g_t2r[8 * 256 * 5376];
__device__ __align__(16) float g_sk1[2 * 8 * 256 * 1024];
__device__ __align__(16) float g_sk2[4 * 8 * 256 * 256];

// ---------------- fp16 weight arena (t-major K layout) -----------------------
#define WOFF_L0  0LL
#define WOFF_L1  131072LL
#define WOFF_L2  393216LL
#define WOFF_FW0 917504LL
#define WOFF_FW1 1507328LL
#define WOFF_FW2 2097152LL
#define WOFF_CW0 2686976LL
#define WOFF_CW1 3276800LL
#define WOFF_CW2 3866624LL
#define WOFF_RW0 4456448LL
#define WOFF_RW1 5046272LL
#define WOFF_RW2 5636096LL
#define WARENA   5672960LL
__device__ __align__(16) ushort g_wh[WARENA];

// ---------------- helpers ----------------------------------------------------
#define SWZ(off)  ((off) ^ (((off) >> 3) & 0x70))   // 128B-row swizzle
#define SWZA(off) ((off) ^ (((off) >> 4) & 0x70))   // 256B-row swizzle

static __device__ __forceinline__ uint32_t smem_u32(const void* p) {
    uint32_t a;
    asm("{ .reg .u64 t; cvta.to.shared.u64 t, %1; cvt.u32.u64 %0, t; }"
        : "=r"(a) : "l"(p));
    return a;
}

#define LDSM_X4(r0, r1, r2, r3, ad) \
    asm volatile("ldmatrix.sync.aligned.m8n8.x4.shared.b16 {%0,%1,%2,%3}, [%4];" \
                 : "=r"(r0), "=r"(r1), "=r"(r2), "=r"(r3) : "r"(ad))
#define LDSM_X4T(r0, r1, r2, r3, ad) \
    asm volatile("ldmatrix.sync.aligned.m8n8.x4.trans.shared.b16 {%0,%1,%2,%3}, [%4];" \
                 : "=r"(r0), "=r"(r1), "=r"(r2), "=r"(r3) : "r"(ad))
#define LDSM_X2(r0, r1, ad) \
    asm volatile("ldmatrix.sync.aligned.m8n8.x2.shared.b16 {%0,%1}, [%2];" \
                 : "=r"(r0), "=r"(r1) : "r"(ad))
#define MMA16816(d, a, b) \
    asm volatile("mma.sync.aligned.m16n8k16.row.col.f32.f16.f16.f32 " \
                 "{%0,%1,%2,%3},{%4,%5,%6,%7},{%8,%9},{%0,%1,%2,%3};" \
                 : "+f"((d)[0]), "+f"((d)[1]), "+f"((d)[2]), "+f"((d)[3]) \
                 : "r"((a)[0]), "r"((a)[1]), "r"((a)[2]), "r"((a)[3]), \
                   "r"((b)[0]), "r"((b)[1]))
#define CVT2HF(dst, hi, lo) \
    asm("cvt.rn.f16x2.f32 %0, %1, %2;" : "=r"(dst) : "f"(hi), "f"(lo))
#define CP_ASYNC16(dst, src) \
    asm volatile("cp.async.cg.shared.global [%0], [%1], 16;" :: "r"(dst), "l"(src))
#define CP_ASYNC8Z(dst, src, sz) \
    asm volatile("cp.async.ca.shared.global [%0], [%1], 8, %2;" \
                 :: "r"(dst), "l"(src), "r"(sz))
#define CP_COMMIT() asm volatile("cp.async.commit_group;" ::: "memory")
#define CP_WAIT0()  asm volatile("cp.async.wait_group 0;" ::: "memory")

static __device__ __forceinline__ ushort f2h(float v) {
    return __half_as_ushort(__float2half_rn(v));
}
static __device__ __forceinline__ float h2f(ushort u) {
    return __half2float(__ushort_as_half(u));
}

// ---------------- merged weight pre-transform --------------------------------
struct WtEnt { const float* src; long long start; int coutA; int cin; int taps; };
struct WtTab { WtEnt e[12]; };

__global__ void wt_all(WtTab T, ushort* __restrict__ wh)
{
    long long idx = (long long)blockIdx.x * 256 + threadIdx.x;
    if (idx >= WARENA) return;
    int i = 0;
#pragma unroll
    for (int j = 1; j < 12; ++j) if (idx >= T.e[j].start) i = j;
    const WtEnt E = T.e[i];
    long long local = idx - E.start;
    const int Kk = E.cin * E.taps;
    long long co = local / Kk;
    int r  = (int)(local - co * Kk);
    int t  = r / E.cin;
    int ci = r - t * E.cin;
    float v = 0.f;
    if (co < E.coutA) v = E.src[co * Kk + (long long)ci * E.taps + t];
    wh[idx] = f2h(v);
}

// ---------------- merged balanced lateral 1x1 GEMMs --------------------------
struct LatEnt {
    const float* in; const ushort* w; const float* bias; void* out;
    int Cin; int logW; long long sliceStride; int split;
};
struct LatTab { LatEnt e[3]; };

__global__ void __launch_bounds__(256, 2)
lat_all(LatTab L)
{
    extern __shared__ char dsm[];
    const int tid = threadIdx.x;
    uint32_t u0  = smem_u32(dsm);
    uint32_t pad = (1024u - (u0 & 1023u)) & 1023u;
    char*    db  = dsm + pad;
    uint32_t dyn = u0 + pad;

    const int bx = blockIdx.x;
    int which, xq, yb;
    if (bx < 64)      { which = 0; xq = bx & 31; yb = bx >> 5; }
    else if (bx < 96) { int l = bx - 64; which = 1; xq = l & 7; yb = l >> 3; }
    else              { int l = bx - 96; which = 2; xq = l & 1; yb = l >> 1; }
    const LatEnt E = L.e[which];

    const int coTile = yb & 1, slice = yb >> 1;
    const int HW = 1 << (2 * E.logW);
    const int co0 = coTile * 128;
    const int bz  = blockIdx.z;
    const int p0  = xq * 128;
    const int c0  = E.split ? slice * 8 : 0;
    const int K   = E.Cin;
    const float* __restrict__ in = E.in;
    const ushort* wh = E.w;

    const int wid = tid >> 5, lane = tid & 31;
    const int m_base = (wid & 3) * 32;
    const int n_base = (wid >> 2) * 64;
    const int g = lane >> 3, lr = lane & 7;

    const uint32_t aA = dyn;
    const uint32_t bA = dyn + 16384;

    float acc[2][8][4];
#pragma unroll
    for (int mt = 0; mt < 2; ++mt)
#pragma unroll
        for (int nt = 0; nt < 8; ++nt)
#pragma unroll
            for (int r = 0; r < 4; ++r) acc[mt][nt][r] = 0.f;

#pragma unroll 1
    for (int cc = 0; cc < 8; ++cc) {
        const int k0 = (c0 + cc) << 6;
#pragma unroll
        for (int j = 0; j < 8; ++j) {
            int idx = tid + j * 256;
            int k = idx >> 5, q = idx & 31;
            const float4 f4 = *(const float4*)(in +
                ((long long)(bz * K + k0 + k)) * HW + p0 + q * 4);
            uint32_t h01, h23;
            CVT2HF(h01, f4.y, f4.x);
            CVT2HF(h23, f4.w, f4.z);
            uint32_t off = SWZA((uint32_t)k * 256u + (uint32_t)q * 8u);
            *(uint2*)(db + off) = make_uint2(h01, h23);
        }
        {
            const char* sH = (const char*)(wh + (long long)co0 * K + k0);
            const long long rowb = (long long)K * 2;
#pragma unroll
            for (int j = 0; j < 4; ++j) {
                int idx = tid + j * 256;
                int r = idx >> 3, c = idx & 7;
                uint4 hv = *(const uint4*)(sH + r * rowb + c * 16);
                uint32_t off = SWZ((uint32_t)r * 128u + (uint32_t)c * 16u);
                *(uint4*)(db + 16384 + off) = hv;
            }
        }
        __syncthreads();

#pragma unroll
        for (int s = 0; s < 4; ++s) {
            uint32_t bh[8][2];
#pragma unroll
            for (int np = 0; np < 4; ++np) {
                int nrow = n_base + np * 16 + (g >> 1) * 8 + lr;
                uint32_t ad = bA + SWZ((uint32_t)(nrow * 128 + s * 32 + (g & 1) * 16));
                LDSM_X4(bh[np*2][0], bh[np*2][1], bh[np*2+1][0], bh[np*2+1][1], ad);
            }
            uint32_t ah[2][4];
#pragma unroll
            for (int mt = 0; mt < 2; ++mt) {
                int krow = s * 16 + (g >> 1) * 8 + lr;
                int colb = (m_base + mt * 16 + (g & 1) * 8) * 2;
                uint32_t ad = aA + SWZA((uint32_t)(krow * 256 + colb));
                LDSM_X4T(ah[mt][0], ah[mt][1], ah[mt][2], ah[mt][3], ad);
            }
#pragma unroll
            for (int mt = 0; mt < 2; ++mt)
#pragma unroll
                for (int nt = 0; nt < 8; ++nt)
                    MMA16816(acc[mt][nt], ah[mt], bh[nt]);
        }
        __syncthreads();
    }

#pragma unroll
    for (int mt = 0; mt < 2; ++mt)
#pragma unroll
        for (int nt = 0; nt < 8; ++nt) {
            if (E.split) {
#pragma unroll
                for (int rg = 0; rg < 4; ++rg) {
                    int m  = m_base + mt * 16 + (lane >> 2) + ((rg >= 2) ? 8 : 0);
                    int co = co0 + n_base + nt * 8 + (lane & 3) * 2 + (rg & 1);
                    long long off = ((long long)(bz * 256 + co)) * HW + p0 + m;
                    ((float*)E.out)[slice * E.sliceStride + off] = acc[mt][nt][rg];
                }
            } else {
#pragma unroll
                for (int r2 = 0; r2 < 2; ++r2) {
                    int m  = m_base + mt * 16 + (lane >> 2) + r2 * 8;
                    int co = co0 + n_base + nt * 8 + (lane & 3) * 2;
                    float v0 = acc[mt][nt][r2 * 2 + 0] + E.bias[co];
                    float v1 = acc[mt][nt][r2 * 2 + 1] + E.bias[co + 1];
                    uint32_t pk = (uint32_t)f2h(v0) | ((uint32_t)f2h(v1) << 16);
                    long long a32 = (((long long)(bz * 64 + (co >> 2))) * HW + p0 + m) * 2
                                    + ((co >> 1) & 1);
                    ((unsigned*)E.out)[a32] = pk;
                }
            }
        }
}

// ---------------- merged split-K reduces (+bias, fp16 quad out) --------------
__global__ void red_all(const float* __restrict__ sk1, const float* __restrict__ sk2,
                        ushort* __restrict__ l1, ushort* __restrict__ l2,
                        const float* __restrict__ b1, const float* __restrict__ b2)
{
    const long long n1 = 8LL * 256 * 1024;
    const long long n2 = 8LL * 256 * 256;
    long long idx = (long long)blockIdx.x * 256 + threadIdx.x;
    if (idx < n1) {
        const int HW = 1024;
        int px = (int)(idx & (HW - 1));
        int co = (int)((idx >> 10) & 255);
        int bz = (int)(idx >> 18);
        float v = b1[co] + sk1[idx] + sk1[n1 + idx];
        l1[(((long long)(bz * 64 + (co >> 2))) * HW + px) * 4 + (co & 3)] = f2h(v);
    } else if (idx < n1 + n2) {
        long long id2 = idx - n1;
        const int HW = 256;
        int px = (int)(id2 & (HW - 1));
        int co = (int)((id2 >> 8) & 255);
        int bz = (int)(id2 >> 16);
        float v = b2[co];
#pragma unroll
        for (int s = 0; s < 4; ++s) v += sk2[s * n2 + id2];
        l2[(((long long)(bz * 64 + (co >> 2))) * HW + px) * 4 + (co & 3)] = f2h(v);
    }
}

// ---------------- nearest 2x upsample + add (fp16 quad domain) ---------------
__global__ void up2add_kernel(unsigned* __restrict__ big,
                              const unsigned* __restrict__ small, int logWs)
{
    const int Ws = 1 << logWs;
    const int W  = Ws * 2;
    const long long total = 8LL * 64 * W * W * 2;
    long long idx = (long long)blockIdx.x * blockDim.x + threadIdx.x;
    if (idx >= total) return;
    int inner2 = (int)(idx & 1);
    long long rest = idx >> 1;
    int x = (int)(rest & (W - 1));
    int y = (int)((rest >> (logWs + 1)) & (W - 1));
    long long bcq = rest >> (2 * logWs + 2);
    unsigned sb = small[(((bcq << logWs) + (y >> 1)) * Ws + (x >> 1)) * 2 + inner2];
    unsigned bb = big[idx];
    float v0 = h2f((ushort)(bb & 0xFFFF)) + h2f((ushort)(sb & 0xFFFF));
    float v1 = h2f((ushort)(bb >> 16))   + h2f((ushort)(sb >> 16));
    big[idx] = (uint32_t)f2h(v0) | ((uint32_t)f2h(v1) << 16);
}

// ---------------- 3x3 tower GEMM: quad-A halo, double-buffered B -------------
struct TArgs {
    const ushort* in[6];
    void* out[6];
    const ushort* wh[6];
    const float* bias[6];
    long long ob[6];
    int coutA[6];
};

#define A_BASE 0u
#define B_BASE 34816u
#define TOWER_DYN 67584
static const size_t TOWER_SMEM = TOWER_DYN + 1024;

template <int NTILE>
static __device__ __forceinline__ void stage_B_async(
    uint32_t bdst, const ushort* wh, int co0, int k0, int tid)
{
    const char* sH = (const char*)(wh + (long long)co0 * 2304 + k0);
    const long long rowb = 4608;
#pragma unroll
    for (int j = 0; j < (NTILE * 8 + 255) / 256; ++j) {
        int idx = tid + j * 256;
        if (idx < NTILE * 8) {
            int r = idx >> 3, c = idx & 7;
            uint32_t off = SWZ((uint32_t)r * 128u + (uint32_t)c * 16u);
            CP_ASYNC16(bdst + off, sH + r * rowb + c * 16);
        }
    }
}

// OUTP=true  : write packed fp16 quad-layout intermediate
// OUTP=false : stage fp32 tile in smem, then fully-coalesced float4 copy to d_out
template <int LVL, int NTILE, bool RELU, bool OUTP>
static __device__ __forceinline__ void tower_body(
    const TArgs& T, char* db, uint32_t dyn,
    int xl, int idx6, int coTile, int tid, int bz)
{
    constexpr int logW = 6 - LVL;
    constexpr int W    = 1 << logW;
    constexpr int padW = W + 2;
    constexpr int imgR = (128 >> logW) + 2;
    constexpr int Rows = imgR * padW;
    constexpr int RowsPad = (Rows + 15) & ~15;
    constexpr int itersA = (RowsPad * 16) / 256;
    constexpr int HW = 1 << (2 * logW);

    const uint2* __restrict__ inq = (const uint2*)T.in[idx6];
    const ushort* wh = T.wh[idx6];
    const float* bias = T.bias[idx6];

    const int p0  = xl * 128;
    const int y0  = p0 >> logW;
    const int co0 = coTile * NTILE;

    constexpr int WN  = NTILE / 2;
    constexpr int N8T = WN / 8;
    const int wid = tid >> 5, lane = tid & 31;
    const int m_base = (wid & 3) * 32;
    const int n_base = (wid >> 2) * WN;
    const int g = lane >> 3, lr = lane & 7;

    float acc[2][N8T][4];
#pragma unroll
    for (int mt = 0; mt < 2; ++mt)
#pragma unroll
        for (int nt = 0; nt < N8T; ++nt)
#pragma unroll
            for (int r = 0; r < 4; ++r) acc[mt][nt][r] = 0.f;

    for (int cic = 0; cic < 4; ++cic) {
        // ---- stage A halo tile via cp.async (zfill on halo OOB) ----
#pragma unroll
        for (int i = 0; i < itersA; ++i) {
            int e = tid + i * 256;
            int j = e / RowsPad;
            int r = e - j * RowsPad;
            int iy = r / padW;
            int ix = r - iy * padW;
            int yi = y0 - 1 + iy;
            int xv = ix - 1;
            bool ok = (r < Rows) && ((unsigned)yi < (unsigned)W) &&
                      ((unsigned)xv < (unsigned)W);
            const uint2* src = ok
                ? inq + ((long long)(bz * 64 + cic * 16 + j)) * HW + yi * W + xv
                : inq;
            uint32_t off = SWZ((uint32_t)r * 128u + (uint32_t)j * 8u);
            CP_ASYNC8Z(dyn + A_BASE + off, src, ok ? 8 : 0);
        }
        stage_B_async<NTILE>(dyn + B_BASE, wh, co0, cic * 64, tid);
        CP_COMMIT();
        CP_WAIT0();
        __syncthreads();

        for (int t = 0; t < 9; ++t) {
            if (t < 8) {
                stage_B_async<NTILE>(dyn + B_BASE + (uint32_t)(((t + 1) & 1) * 16384),
                                     wh, co0, (t + 1) * 256 + cic * 64, tid);
                CP_COMMIT();
            }
            const uint32_t bA = dyn + B_BASE + (uint32_t)((t & 1) * 16384);

            const int dy = t / 3 - 1;
            const int dx = t - (t / 3) * 3 - 1;
            int prow[2];
#pragma unroll
            for (int mt = 0; mt < 2; ++mt) {
                int m = m_base + mt * 16 + ((g & 1) << 3) + lr;
                prow[mt] = (1 + (m >> logW) + dy) * padW + (m & (W - 1)) + 1 + dx;
            }
            const int colA0 = (g >> 1) * 16;

#pragma unroll
            for (int s = 0; s < 4; ++s) {
                uint32_t bh[N8T][2];
                if constexpr (N8T == 1) {
                    uint32_t ad = bA +
                        SWZ((uint32_t)((n_base + lr) * 128 + s * 32 + (g & 1) * 16));
                    LDSM_X2(bh[0][0], bh[0][1], ad);
                } else {
#pragma unroll
                    for (int np = 0; np < N8T / 2; ++np) {
                        int nrow = n_base + np * 16 + (g >> 1) * 8 + lr;
                        uint32_t ad = bA +
                            SWZ((uint32_t)(nrow * 128 + s * 32 + (g & 1) * 16));
                        LDSM_X4(bh[np*2][0], bh[np*2][1], bh[np*2+1][0], bh[np*2+1][1], ad);
                    }
                }
                uint32_t ah[2][4];
#pragma unroll
                for (int mt = 0; mt < 2; ++mt) {
                    uint32_t ad = dyn + A_BASE +
                        SWZ((uint32_t)(prow[mt] * 128 + s * 32 + colA0));
                    LDSM_X4(ah[mt][0], ah[mt][1], ah[mt][2], ah[mt][3], ad);
                }
#pragma unroll
                for (int mt = 0; mt < 2; ++mt)
#pragma unroll
                    for (int nt = 0; nt < N8T; ++nt)
                        MMA16816(acc[mt][nt], ah[mt], bh[nt]);
            }
            if (t < 8) CP_WAIT0();
            __syncthreads();
        }
    }

    // ---- epilogue ----
    if constexpr (OUTP) {
#pragma unroll
        for (int mt = 0; mt < 2; ++mt)
#pragma unroll
            for (int nt = 0; nt < N8T; ++nt)
#pragma unroll
                for (int r2 = 0; r2 < 2; ++r2) {
                    int m  = m_base + mt * 16 + (lane >> 2) + r2 * 8;
                    int co = co0 + n_base + nt * 8 + (lane & 3) * 2;
                    float v0 = acc[mt][nt][r2 * 2 + 0] + bias[co];
                    float v1 = acc[mt][nt][r2 * 2 + 1] + bias[co + 1];
                    if (RELU) { v0 = fmaxf(v0, 0.f); v1 = fmaxf(v1, 0.f); }
                    uint32_t pk = (uint32_t)f2h(v0) | ((uint32_t)f2h(v1) << 16);
                    long long a32 = (((long long)(bz * 64 + (co >> 2))) * HW + p0 + m) * 2
                                    + ((co >> 1) & 1);
                    ((unsigned*)T.out[idx6])[a32] = pk;
                }
    } else {
        float* st = (float*)db;
#pragma unroll
        for (int mt = 0; mt < 2; ++mt)
#pragma unroll
            for (int nt = 0; nt < N8T; ++nt)
#pragma unroll
                for (int r2 = 0; r2 < 2; ++r2) {
                    int m    = m_base + mt * 16 + (lane >> 2) + r2 * 8;
                    int cloc = n_base + nt * 8 + (lane & 3) * 2;
                    float v0 = acc[mt][nt][r2 * 2 + 0] + bias[co0 + cloc];
                    float v1 = acc[mt][nt][r2 * 2 + 1] + bias[co0 + cloc + 1];
                    *(float2*)&st[m * 132 + cloc] = make_float2(v0, v1);
                }
        __syncthreads();
        int cols = T.coutA[idx6] - co0;
        if (cols > NTILE) cols = NTILE;
        const int q4 = cols >> 2;
        float* dst = (float*)T.out[idx6] + (long long)bz * T.ob[idx6] + co0;
        for (int e = tid; e < 128 * q4; e += 256) {
            int m  = e / q4;
            int c4 = e - m * q4;
            float4 v = *(float4*)&st[m * 132 + c4 * 4];
            *(float4*)(dst + (long long)(p0 + m) * 252 + c4 * 4) = v;
        }
    }
}

template <int NTILE, bool RELU, bool OUTP>
__global__ void __launch_bounds__(256, 2)
tower_gemm(TArgs T)
{
    extern __shared__ char dsm[];
    const int tid = threadIdx.x;
    uint32_t u0  = smem_u32(dsm);
    uint32_t padB = (1024u - (u0 & 1023u)) & 1023u;
    char*    db  = dsm + padB;
    uint32_t dyn = u0 + padB;

    const int xb  = blockIdx.x;
    const int lvl = (xb >= 40) ? 2 : ((xb >= 32) ? 1 : 0);
    const int xl  = xb - ((lvl == 2) ? 40 : ((lvl == 1) ? 32 : 0));
    const int yb  = blockIdx.y;
    const int set = yb >> 1;
    const int coTile = yb & 1;
    const int idx6 = set * 3 + lvl;
    const int bz  = blockIdx.z;

    if (lvl == 0)
        tower_body<0, NTILE, RELU, OUTP>(T, db, dyn, xl, idx6, coTile, tid, bz);
    else if (lvl == 1)
        tower_body<1, NTILE, RELU, OUTP>(T, db, dyn, xl, idx6, coTile, tid, bz);
    else
        tower_body<2, NTILE, RELU, OUTP>(T, db, dyn, xl, idx6, coTile, tid, bz);
}

// merged finals: y in {0,1} -> cls (NTILE=128, set 0); y == 2 -> reg (NTILE=16, set 1)
__global__ void __launch_bounds__(256, 2)
tower_finals(TArgs T)
{
    extern __shared__ char dsm[];
    const int tid = threadIdx.x;
    uint32_t u0  = smem_u32(dsm);
    uint32_t padB = (1024u - (u0 & 1023u)) & 1023u;
    char*    db  = dsm + padB;
    uint32_t dyn = u0 + padB;

    const int xb  = blockIdx.x;
    const int lvl = (xb >= 40) ? 2 : ((xb >= 32) ? 1 : 0);
    const int xl  = xb - ((lvl == 2) ? 40 : ((lvl == 1) ? 32 : 0));
    const int yb  = blockIdx.y;
    const int bz  = blockIdx.z;

    if (yb < 2) {
        const int idx6 = lvl;
        if (lvl == 0)      tower_body<0, 128, false, false>(T, db, dyn, xl, idx6, yb, tid, bz);
        else if (lvl == 1) tower_body<1, 128, false, false>(T, db, dyn, xl, idx6, yb, tid, bz);
        else               tower_body<2, 128, false, false>(T, db, dyn, xl, idx6, yb, tid, bz);
    } else {
        const int idx6 = 3 + lvl;
        if (lvl == 0)      tower_body<0, 16, false, false>(T, db, dyn, xl, idx6, 0, tid, bz);
        else if (lvl == 1) tower_body<1, 16, false, false>(T, db, dyn, xl, idx6, 0, tid, bz);
        else               tower_body<2, 16, false, false>(T, db, dyn, xl, idx6, 0, tid, bz);
    }
}

// ---------------- anchors ----------------------------------------------------
__global__ void anchors_kernel(float* __restrict__ out)
{
    int i = blockIdx.x * blockDim.x + threadIdx.x;
    if (i >= 16128) return;
    int lvl, rem;
    if (i < 12288)      { lvl = 0; rem = i; }
    else if (i < 15360) { lvl = 1; rem = i - 12288; }
    else                { lvl = 2; rem = i - 15360; }
    const int w        = 64 >> lvl;
    const float stride = 8.0f * (float)(1 << lvl);
    const float bs     = 32.0f * (float)(1 << lvl);
    const int a = rem % 3;
    const int s = rem / 3;
    const int x = s % w;
    const int y = s / w;
    const float sq[3] = {0.70710678118654752f, 1.0f, 1.41421356237309505f};
    const float hw = bs * sq[a] * 0.5f;
    const float hh = bs / sq[a] * 0.5f;
    const float cx = (float)x * stride;
    const float cy = (float)y * stride;
    float* o = out + (long long)i * 4;
    o[0] = cx - hw; o[1] = cy - hh; o[2] = cx + hw; o[3] = cy + hh;
}

// ---------------- host dispatch ----------------------------------------------
static const size_t LAT_SMEM = 33792;

extern "C" void kernel_launch(void* const* d_in, const int* in_sizes, int n_in,
                              void* d_out, int out_size)
{
    const float* feat3 = (const float*)d_in[0];
    const float* feat4 = (const float*)d_in[1];
    const float* feat5 = (const float*)d_in[2];
    const float* lw0 = (const float*)d_in[3];  const float* lb0 = (const float*)d_in[4];
    const float* lw1 = (const float*)d_in[5];  const float* lb1 = (const float*)d_in[6];
    const float* lw2 = (const float*)d_in[7];  const float* lb2 = (const float*)d_in[8];
    const float* fw0 = (const float*)d_in[9];  const float* fb0 = (const float*)d_in[10];
    const float* fw1 = (const float*)d_in[11]; const float* fb1 = (const float*)d_in[12];
    const float* fw2 = (const float*)d_in[13]; const float* fb2 = (const float*)d_in[14];
    const float* cw0 = (const float*)d_in[15]; const float* cb0 = (const float*)d_in[16];
    const float* cw1 = (const float*)d_in[17]; const float* cb1 = (const float*)d_in[18];
    const float* cw2 = (const float*)d_in[19]; const float* cb2 = (const float*)d_in[20];
    const float* rw0 = (const float*)d_in[21]; const float* rb0 = (const float*)d_in[22];
    const float* rw1 = (const float*)d_in[23]; const float* rb1 = (const float*)d_in[24];
    const float* rw2 = (const float*)d_in[25]; const float* rb2 = (const float*)d_in[26];
    float* out = (float*)d_out;

    cudaFuncSetAttribute(lat_all, cudaFuncAttributeMaxDynamicSharedMemorySize, (int)LAT_SMEM);
    cudaFuncSetAttribute(tower_gemm<128, false, true>, cudaFuncAttributeMaxDynamicSharedMemorySize, (int)TOWER_SMEM);
    cudaFuncSetAttribute(tower_gemm<128, true,  true>, cudaFuncAttributeMaxDynamicSharedMemorySize, (int)TOWER_SMEM);
    cudaFuncSetAttribute(tower_finals, cudaFuncAttributeMaxDynamicSharedMemorySize, (int)TOWER_SMEM);

    ushort *l0, *l1, *l2, *f, *t1c, *t1r, *t2c, *t2r, *wh;
    float *sk1, *sk2;
    cudaGetSymbolAddress((void**)&l0,  g_l0);
    cudaGetSymbolAddress((void**)&l1,  g_l1);
    cudaGetSymbolAddress((void**)&l2,  g_l2);
    cudaGetSymbolAddress((void**)&f,   g_f);
    cudaGetSymbolAddress((void**)&t1c, g_t1c);
    cudaGetSymbolAddress((void**)&t1r, g_t1r);
    cudaGetSymbolAddress((void**)&t2c, g_t2c);
    cudaGetSymbolAddress((void**)&t2r, g_t2r);
    cudaGetSymbolAddress((void**)&sk1, g_sk1);
    cudaGetSymbolAddress((void**)&sk2, g_sk2);
    cudaGetSymbolAddress((void**)&wh,  g_wh);

    {
        WtTab T;
        const WtEnt ents[12] = {
            { lw0, WOFF_L0,  256, 512,  1 },
            { lw1, WOFF_L1,  256, 1024, 1 },
            { lw2, WOFF_L2,  256, 2048, 1 },
            { fw0, WOFF_FW0, 256, 256,  9 },
            { fw1, WOFF_FW1, 256, 256,  9 },
            { fw2, WOFF_FW2, 256, 256,  9 },
            { cw0, WOFF_CW0, 256, 256,  9 },
            { cw1, WOFF_CW1, 256, 256,  9 },
            { cw2, WOFF_CW2, 240, 256,  9 },
            { rw0, WOFF_RW0, 256, 256,  9 },
            { rw1, WOFF_RW1, 256, 256,  9 },
            { rw2, WOFF_RW2, 12,  256,  9 },
        };
        for (int i = 0; i < 12; ++i) T.e[i] = ents[i];
        wt_all<<<(unsigned)((WARENA + 255) / 256), 256>>>(T, wh);
    }

    // ---- merged balanced FPN laterals ----
    {
        LatTab L;
        L.e[0] = { feat3, wh + WOFF_L0, lb0, l0,  512,  6, 0, 0 };
        L.e[1] = { feat4, wh + WOFF_L1, lb1, sk1, 1024, 5, 8LL * 256 * 1024, 1 };
        L.e[2] = { feat5, wh + WOFF_L2, lb2, sk2, 2048, 4, 8LL * 256 * 256,  1 };
        lat_all<<<dim3(112, 1, 8), 256, LAT_SMEM>>>(L);
    }
    {
        long long n = 8LL * 256 * 1024 + 8LL * 256 * 256;
        red_all<<<(unsigned)((n + 255) / 256), 256>>>(sk1, sk2, l1, l2, lb1, lb2);
    }
    {
        long long n1 = 8LL * 64 * 32 * 32 * 2;
        up2add_kernel<<<(unsigned)((n1 + 255) / 256), 256>>>(
            (unsigned*)l1, (const unsigned*)l2, 4);
        long long n0 = 8LL * 64 * 64 * 64 * 2;
        up2add_kernel<<<(unsigned)((n0 + 255) / 256), 256>>>(
            (unsigned*)l0, (const unsigned*)l1, 5);
    }

    auto setSlot = [&](TArgs& T, int s, const ushort* i0, const ushort* i1,
                       const ushort* i2, void* o0, void* o1, void* o2,
                       long long woff, const float* b, int coutA) {
        T.in[s*3+0] = i0; T.in[s*3+1] = i1; T.in[s*3+2] = i2;
        T.out[s*3+0] = o0; T.out[s*3+1] = o1; T.out[s*3+2] = o2;
        for (int l = 0; l < 3; ++l) {
            T.wh[s*3+l] = wh + woff;
            T.bias[s*3+l] = b;
            T.ob[s*3+l] = 5376LL * 252;
            T.coutA[s*3+l] = coutA;
        }
    };

    // FPN 3x3 output convs (per-level weights)
    {
        TArgs T;
        T.in[0] = l0; T.in[1] = l1; T.in[2] = l2;
        T.out[0] = f; T.out[1] = f + SEG1; T.out[2] = f + SEG2;
        const long long wo[3] = { WOFF_FW0, WOFF_FW1, WOFF_FW2 };
        const float* bb[3] = { fb0, fb1, fb2 };
        for (int l = 0; l < 3; ++l) {
            T.wh[l] = wh + wo[l]; T.bias[l] = bb[l];
            T.ob[l] = 0; T.coutA[l] = 256;
        }
        tower_gemm<128, false, true><<<dim3(42, 2, 8), 256, TOWER_SMEM>>>(T);
    }
    // conv1 fused (cls set 0, reg set 1)
    {
        TArgs T;
        setSlot(T, 0, f, f + SEG1, f + SEG2, t1c, t1c + SEG1, t1c + SEG2, WOFF_CW0, cb0, 256);
        setSlot(T, 1, f, f + SEG1, f + SEG2, t1r, t1r + SEG1, t1r + SEG2, WOFF_RW0, rb0, 256);
        tower_gemm<128, true, true><<<dim3(42, 4, 8), 256, TOWER_SMEM>>>(T);
    }
    // conv2 fused
    {
        TArgs T;
        setSlot(T, 0, t1c, t1c + SEG1, t1c + SEG2, t2c, t2c + SEG1, t2c + SEG2, WOFF_CW1, cb1, 256);
        setSlot(T, 1, t1r, t1r + SEG1, t1r + SEG2, t2r, t2r + SEG1, t2r + SEG2, WOFF_RW1, rb1, 256);
        tower_gemm<128, true, true><<<dim3(42, 4, 8), 256, TOWER_SMEM>>>(T);
    }
    // merged finals: cls (y=0,1) + reg (y=2)
    {
        TArgs T;
        setSlot(T, 0, t2c, t2c + SEG1, t2c + SEG2,
                out, out + 4096LL * 252, out + 5120LL * 252, WOFF_CW2, cb2, 240);
        setSlot(T, 1, t2r, t2r + SEG1, t2r + SEG2,
                out + 240, out + 4096LL * 252 + 240, out + 5120LL * 252 + 240,
                WOFF_RW2, rb2, 12);
        tower_finals<<<dim3(42, 3, 8), 256, TOWER_SMEM>>>(T);
    }

    anchors_kernel<<<(16128 + 255) / 256, 256>>>(out + 10838016LL);
}